// round 7
// baseline (speedup 1.0000x reference)
#include <cuda_runtime.h>
#include <cstdint>

namespace {

constexpr int NUM_HEADS = 14;
constexpr int BROWS  = 1024;
constexpr int DIN    = 1920;
constexpr int DSLICE = 128;
constexpr int HID    = NUM_HEADS * DSLICE;   // 1792
constexpr int PMAX   = 36928;

constexpr int BM = 128, BN = 128, BK = 32;
constexpr int SST = BK + 4;

__constant__ int c_p[NUM_HEADS] =
    {9280,18496,36928,36928,36928,36928,36928,36928,36928,18496,9280,18496,18496,9280};
__constant__ int c_tile_start[NUM_HEADS] =
    {0,73,218,507,796,1085,1374,1663,1952,2241,2386,2459,2604,2749};
__constant__ int c_cum[NUM_HEADS] =
    {0,9280,27776,64704,101632,138560,175488,212416,249344,286272,304768,314048,332544,351040};

constexpr int TOTAL_NTILES = 2822;
constexpr int MTILES = BROWS / BM;           // 8 (kernel A)
constexpr int ITERS  = 4;                    // kernel B: 4 x 256-row iterations

constexpr int ATILE256 = 256 * DSLICE;       // 32768 floats = 128KB per 256-row A tile
constexpr int HALF_FLOATS = ATILE256 / 2;    // 16384 (ksteps 0-7 contiguous)
constexpr int BTILE = BN * DSLICE;           // 16384 floats

// head smem: B 64KB + A half-buffers 2x64KB
constexpr size_t HEAD_SMEM_BYTES = (size_t)(BTILE + ATILE256) * sizeof(float); // 196608

// hidden activations, A-fragment-major 256-row tiles: [head][iter][32768]
__device__ float g_hfrag[(size_t)NUM_HEADS * ITERS * ATILE256];

__device__ __forceinline__ uint32_t f2tf32(float f) {
    uint32_t r;
    asm("cvt.rna.tf32.f32 %0, %1;" : "=r"(r) : "f"(f));
    return r;
}

__device__ __forceinline__ void mma_tf32(float* c, const uint32_t* a, const uint32_t* b) {
    asm volatile(
        "mma.sync.aligned.m16n8k8.row.col.f32.tf32.tf32.f32 "
        "{%0,%1,%2,%3}, {%4,%5,%6,%7}, {%8,%9}, {%0,%1,%2,%3};\n"
        : "+f"(c[0]), "+f"(c[1]), "+f"(c[2]), "+f"(c[3])
        : "r"(a[0]), "r"(a[1]), "r"(a[2]), "r"(a[3]),
          "r"(b[0]), "r"(b[1]));
}

__device__ __forceinline__ void cp_async16_s(uint32_t dst_smem, const float* src) {
    asm volatile("cp.async.cg.shared.global [%0], [%1], 16;\n" :: "r"(dst_smem), "l"(src));
}

// A-fragment-major float index within a 256-row x 128-k tile.
// float4 idx = (kstep*16 + rb)*32 + (lr<<2)+la3 ; elem = er + 2*ec
__device__ __forceinline__ int afrag_idx(int m, int k) {
    int rb = m >> 4, m16 = m & 15, lr = m16 & 7, er = m16 >> 3;
    int kstep = k >> 3, k8 = k & 7, la3 = k8 & 3, ec = k8 >> 2;
    return ((((kstep << 4) + rb) * 32 + (lr << 2) + la3) << 2) + er + (ec << 1);
}

// B-fragment-major float index (128 out-cols x 128 k), wn groups of 32 cols.
// float4 idx = ((kstep*4 + wn)*2 + jp)*32 + (lr<<2)+la3 ; elem = (j&1)*2 + (k8>=4)
__device__ __forceinline__ int bfrag_idx(int row, int k) {
    int wn = row >> 5, j = (row & 31) >> 3, lr = row & 7;
    int kstep = k >> 3, la3 = k & 3, b1 = ((k & 7) >= 4);
    return (((((kstep << 2) + wn) << 1) + (j >> 1)) * 32 + (lr << 2) + la3) * 4
           + ((j & 1) << 1) + b1;
}

// ---------------------------------------------------------------------------
// Kernel A: hidden = relu(x @ W_hidden^T + b_hidden), tf32-rounded,
//           written into 256-row A-fragment-major tiles g_hfrag[h][it][...]
// ---------------------------------------------------------------------------
__global__ void __launch_bounds__(256)
hidden_gemm(const float* __restrict__ x,
            const float* __restrict__ Wh,
            const float* __restrict__ bh)
{
    __shared__ float As[BM][SST];
    __shared__ float Bs[BN][SST];

    const int mtile = blockIdx.x & 7;
    const int ntile = blockIdx.x >> 3;       // head index
    const int m0 = mtile * BM;
    const int n0 = ntile * BN;

    const int tid  = threadIdx.x;
    const int lane = tid & 31;
    const int warp = tid >> 5;
    const int wm = warp >> 1;
    const int wn = warp & 1;

    float acc[2][8][4];
    #pragma unroll
    for (int t = 0; t < 2; ++t)
        #pragma unroll
        for (int j = 0; j < 8; ++j)
            #pragma unroll
            for (int q = 0; q < 4; ++q) acc[t][j][q] = 0.f;

    for (int k0 = 0; k0 < DIN; k0 += BK) {
        #pragma unroll
        for (int it = 0; it < 4; ++it) {
            int slot = tid + it * 256;
            int r  = slot >> 3;
            int c4 = (slot & 7) * 4;
            float4 va = *reinterpret_cast<const float4*>(
                x + (size_t)(m0 + r) * DIN + k0 + c4);
            As[r][c4 + 0] = __uint_as_float(f2tf32(va.x));
            As[r][c4 + 1] = __uint_as_float(f2tf32(va.y));
            As[r][c4 + 2] = __uint_as_float(f2tf32(va.z));
            As[r][c4 + 3] = __uint_as_float(f2tf32(va.w));
            float4 vb = *reinterpret_cast<const float4*>(
                Wh + (size_t)(n0 + r) * DIN + k0 + c4);
            Bs[r][c4 + 0] = __uint_as_float(f2tf32(vb.x));
            Bs[r][c4 + 1] = __uint_as_float(f2tf32(vb.y));
            Bs[r][c4 + 2] = __uint_as_float(f2tf32(vb.z));
            Bs[r][c4 + 3] = __uint_as_float(f2tf32(vb.w));
        }
        __syncthreads();

        #pragma unroll
        for (int ks = 0; ks < BK; ks += 8) {
            uint32_t a[2][4];
            #pragma unroll
            for (int t = 0; t < 2; ++t) {
                int row = wm * 32 + t * 16 + (lane >> 2);
                int kc  = ks + (lane & 3);
                a[t][0] = __float_as_uint(As[row][kc]);
                a[t][1] = __float_as_uint(As[row + 8][kc]);
                a[t][2] = __float_as_uint(As[row][kc + 4]);
                a[t][3] = __float_as_uint(As[row + 8][kc + 4]);
            }
            #pragma unroll
            for (int j = 0; j < 8; ++j) {
                int col = wn * 64 + j * 8 + (lane >> 2);
                int kc  = ks + (lane & 3);
                uint32_t b[2];
                b[0] = __float_as_uint(Bs[col][kc]);
                b[1] = __float_as_uint(Bs[col][kc + 4]);
                mma_tf32(acc[0][j], a[0], b);
                mma_tf32(acc[1][j], a[1], b);
            }
        }
        __syncthreads();
    }

    // Epilogue: bias + relu + tf32 round, scatter into 256-row A-fragment tile.
    const int it    = mtile >> 1;
    const int rbase = (mtile & 1) * 128;
    float* Hf = g_hfrag + ((size_t)ntile * ITERS + it) * ATILE256;
    const int lr2  = lane >> 2;
    const int la32 = lane & 3;
    #pragma unroll
    for (int t = 0; t < 2; ++t) {
        #pragma unroll
        for (int j = 0; j < 8; ++j) {
            int kbase = wn * 64 + j * 8 + 2 * la32;
            float b0 = bh[n0 + kbase], b1 = bh[n0 + kbase + 1];
            int mA = rbase + wm * 32 + t * 16 + lr2;     // rows mA, mA+8
            Hf[afrag_idx(mA,     kbase    )] =
                __uint_as_float(f2tf32(fmaxf(acc[t][j][0] + b0, 0.f)));
            Hf[afrag_idx(mA,     kbase + 1)] =
                __uint_as_float(f2tf32(fmaxf(acc[t][j][1] + b1, 0.f)));
            Hf[afrag_idx(mA + 8, kbase    )] =
                __uint_as_float(f2tf32(fmaxf(acc[t][j][2] + b0, 0.f)));
            Hf[afrag_idx(mA + 8, kbase + 1)] =
                __uint_as_float(f2tf32(fmaxf(acc[t][j][3] + b1, 0.f)));
        }
    }
}

// ---------------------------------------------------------------------------
// Kernel B: 512 threads (16 warps, 4/SMSP). One CTA per 128-col N-tile,
//   4 x 256-row M iterations. B fragment-major resident in smem; A streamed
//   as 64KB k-half buffers via cp.async (2-deep pipeline).
// ---------------------------------------------------------------------------
__global__ void __launch_bounds__(512, 1)
head_gemm(const float* __restrict__ Wheads,
          const float* __restrict__ bheads,
          float* __restrict__ out)
{
    extern __shared__ float smem[];
    float* sB = smem;                        // 16384 floats
    float* sA = smem + BTILE;                // 2 x 16384 floats (half-buffers)

    const int ntg = blockIdx.x;
    int h = 0;
    #pragma unroll
    for (int i = 1; i < NUM_HEADS; ++i) h += (ntg >= c_tile_start[i]);
    const int ntile = ntg - c_tile_start[h];
    const int p  = c_p[h];
    const int n0 = ntile * BN;

    const float* Bg    = Wheads + (size_t)h * PMAX * DSLICE;
    const float* bias  = bheads + (size_t)h * PMAX;
    float* Og = out + (size_t)c_cum[h] * BROWS;
    const float* Hf = g_hfrag + (size_t)h * ITERS * ATILE256;

    const int tid  = threadIdx.x;
    const int lane = tid & 31;
    const int warp = tid >> 5;
    const int wm = warp >> 2;   // 0..3 (64 rows each)
    const int wn = warp & 3;    // 0..3 (32 cols each)
    const int la3 = lane & 3;
    const int lr  = lane >> 2;

    const uint32_t sA_u = (uint32_t)__cvta_generic_to_shared(sA);

    // prologue: prefetch halves s=0 (it0,ks0-7 -> buf0) and s=1 (it0,ks8-15 -> buf1)
    #pragma unroll
    for (int g = 0; g < 2; ++g) {
        const float* src = Hf + (size_t)g * HALF_FLOATS;
        uint32_t dst = sA_u + (uint32_t)g * HALF_FLOATS * 4;
        #pragma unroll
        for (int it2 = 0; it2 < 8; ++it2) {
            int fo = (it2 * 512 + tid) * 4;
            cp_async16_s(dst + fo * 4, src + fo);
        }
        asm volatile("cp.async.commit_group;\n");
    }

    // B tile -> fragment-major smem (once)
    #pragma unroll
    for (int it2 = 0; it2 < 8; ++it2) {
        int slot = it2 * 512 + tid;          // 0..4095
        int row = slot >> 5;
        int k4  = (slot & 31) * 4;
        float4 v;
        if (n0 + row < p) {
            v = *reinterpret_cast<const float4*>(Bg + (size_t)(n0 + row) * DSLICE + k4);
        } else {
            v = make_float4(0.f, 0.f, 0.f, 0.f);
        }
        sB[bfrag_idx(row, k4    )] = __uint_as_float(f2tf32(v.x));
        sB[bfrag_idx(row, k4 + 1)] = __uint_as_float(f2tf32(v.y));
        sB[bfrag_idx(row, k4 + 2)] = __uint_as_float(f2tf32(v.z));
        sB[bfrag_idx(row, k4 + 3)] = __uint_as_float(f2tf32(v.w));
    }

    // hoist bias
    float bs0[4], bs1[4];
    #pragma unroll
    for (int j = 0; j < 4; ++j) {
        int col = n0 + wn * 32 + j * 8 + 2 * la3;
        bs0[j] = (col < p) ? bias[col]     : 0.f;
        bs1[j] = (col < p) ? bias[col + 1] : 0.f;
    }

    const float4* sB4 = reinterpret_cast<const float4*>(sB);

    asm volatile("cp.async.wait_group 1;\n" ::: "memory");   // buf0 ready
    __syncthreads();

    for (int it = 0; it < ITERS; ++it) {
        float acc[4][4][4];
        #pragma unroll
        for (int t = 0; t < 4; ++t)
            #pragma unroll
            for (int j = 0; j < 4; ++j)
                #pragma unroll
                for (int q = 0; q < 4; ++q) acc[t][j][q] = 0.f;

        #pragma unroll
        for (int half = 0; half < 2; ++half) {
            const float4* sA4 = reinterpret_cast<const float4*>(sA + half * HALF_FLOATS);

            // compute 8 local ksteps on this half-buffer
            #pragma unroll
            for (int ls = 0; ls < 8; ++ls) {
                const int ks = half * 8 + ls;
                float4 af[4];
                #pragma unroll
                for (int t = 0; t < 4; ++t)
                    af[t] = sA4[(ls * 16 + wm * 4 + t) * 32 + lane];
                float4 bf0 = sB4[((ks * 4 + wn) * 2 + 0) * 32 + lane];
                float4 bf1 = sB4[((ks * 4 + wn) * 2 + 1) * 32 + lane];
                const uint32_t* b0p = reinterpret_cast<const uint32_t*>(&bf0);
                const uint32_t* b1p = reinterpret_cast<const uint32_t*>(&bf1);
                uint32_t bj0[2] = {b0p[0], b0p[1]};
                uint32_t bj1[2] = {b0p[2], b0p[3]};
                uint32_t bj2[2] = {b1p[0], b1p[1]};
                uint32_t bj3[2] = {b1p[2], b1p[3]};
                #pragma unroll
                for (int t = 0; t < 4; ++t) {
                    const uint32_t* ap = reinterpret_cast<const uint32_t*>(&af[t]);
                    mma_tf32(acc[t][0], ap, bj0);
                    mma_tf32(acc[t][1], ap, bj1);
                    mma_tf32(acc[t][2], ap, bj2);
                    mma_tf32(acc[t][3], ap, bj3);
                }
            }

            const int s = it * 2 + half;
            // free this half-buffer, then refill it with half s+2
            if (s + 2 <= 7) {
                __syncthreads();
                const float* src = Hf + (size_t)(s + 2) * HALF_FLOATS;
                uint32_t dst = sA_u + (uint32_t)half * HALF_FLOATS * 4;
                #pragma unroll
                for (int it2 = 0; it2 < 8; ++it2) {
                    int fo = (it2 * 512 + tid) * 4;
                    cp_async16_s(dst + fo * 4, src + fo);
                }
                asm volatile("cp.async.commit_group;\n");
            }

            // epilogue for this 256-row iteration (overlaps the in-flight loads)
            if (half == 1) {
                const int m0 = it * 256;
                #pragma unroll
                for (int t = 0; t < 4; ++t) {
                    int row = m0 + wm * 64 + t * 16 + lr;
                    #pragma unroll
                    for (int j = 0; j < 4; ++j) {
                        int col = n0 + wn * 32 + j * 8 + 2 * la3;
                        if (col < p) {
                            float2 v0 = make_float2(acc[t][j][0] + bs0[j],
                                                    acc[t][j][1] + bs1[j]);
                            float2 v1 = make_float2(acc[t][j][2] + bs0[j],
                                                    acc[t][j][3] + bs1[j]);
                            *reinterpret_cast<float2*>(&Og[(size_t)row * p + col])       = v0;
                            *reinterpret_cast<float2*>(&Og[(size_t)(row + 8) * p + col]) = v1;
                        }
                    }
                }
            }

            // make the other half-buffer (half s+1's data) visible before next compute
            if (s < 6) {
                asm volatile("cp.async.wait_group 1;\n" ::: "memory");
                __syncthreads();
            } else if (s == 6) {
                asm volatile("cp.async.wait_group 0;\n" ::: "memory");
                __syncthreads();
            }
        }
    }
}

} // anonymous namespace

extern "C" void kernel_launch(void* const* d_in, const int* in_sizes, int n_in,
                              void* d_out, int out_size) {
    (void)in_sizes; (void)n_in; (void)out_size;
    const float* x      = (const float*)d_in[0];
    const float* Wh     = (const float*)d_in[1];
    const float* bh     = (const float*)d_in[2];
    const float* Wheads = (const float*)d_in[3];
    const float* bheads = (const float*)d_in[4];
    float* out = (float*)d_out;

    static bool attr_set = false;
    if (!attr_set) {
        cudaFuncSetAttribute(head_gemm,
                             cudaFuncAttributeMaxDynamicSharedMemorySize,
                             (int)HEAD_SMEM_BYTES);
        attr_set = true;
    }

    hidden_gemm<<<MTILES * (HID / BN), 256>>>(x, Wh, bh);
    head_gemm<<<TOTAL_NTILES, 512, HEAD_SMEM_BYTES>>>(Wheads, bheads, out);
}

// round 8
// speedup vs baseline: 1.0572x; 1.0572x over previous
#include <cuda_runtime.h>
#include <cstdint>

namespace {

constexpr int NUM_HEADS = 14;
constexpr int BROWS  = 1024;
constexpr int DIN    = 1920;
constexpr int DSLICE = 128;
constexpr int HID    = NUM_HEADS * DSLICE;   // 1792
constexpr int PMAX   = 36928;

constexpr int BM = 128, BN = 128, BK = 32;
constexpr int SST = BK + 4;

__constant__ int c_p[NUM_HEADS] =
    {9280,18496,36928,36928,36928,36928,36928,36928,36928,18496,9280,18496,18496,9280};
__constant__ int c_tile_start[NUM_HEADS] =
    {0,73,218,507,796,1085,1374,1663,1952,2241,2386,2459,2604,2749};
__constant__ int c_cum[NUM_HEADS] =
    {0,9280,27776,64704,101632,138560,175488,212416,249344,286272,304768,314048,332544,351040};

constexpr int TOTAL_NTILES = 2822;
constexpr int MTILES = BROWS / BM;           // 8

constexpr int TILE_FLOATS = BM * DSLICE;     // 16384 floats = 64KB per tile

// head smem: B 64KB + A double-buffer 2x64KB
constexpr size_t HEAD_SMEM_BYTES = (size_t)(3 * TILE_FLOATS) * sizeof(float); // 196608

// hidden activations in A-FRAGMENT-MAJOR 128-row tiles: [head][mtile][16384]
__device__ float g_hfrag[(size_t)NUM_HEADS * MTILES * TILE_FLOATS];

__device__ __forceinline__ uint32_t f2tf32(float f) {
    uint32_t r;
    asm("cvt.rna.tf32.f32 %0, %1;" : "=r"(r) : "f"(f));
    return r;
}

__device__ __forceinline__ void mma_tf32(float* c, const uint32_t* a, const uint32_t* b) {
    asm volatile(
        "mma.sync.aligned.m16n8k8.row.col.f32.tf32.tf32.f32 "
        "{%0,%1,%2,%3}, {%4,%5,%6,%7}, {%8,%9}, {%0,%1,%2,%3};\n"
        : "+f"(c[0]), "+f"(c[1]), "+f"(c[2]), "+f"(c[3])
        : "r"(a[0]), "r"(a[1]), "r"(a[2]), "r"(a[3]),
          "r"(b[0]), "r"(b[1]));
}

__device__ __forceinline__ void cp_async16_s(uint32_t dst_smem, const float* src) {
    asm volatile("cp.async.cg.shared.global [%0], [%1], 16;\n" :: "r"(dst_smem), "l"(src));
}

// A-fragment-major float index within a 128x128 tile (R6 layout, verified).
// float4 idx = (kstep*8 + rb)*32 + lane ; elem = er + 2*ec
__device__ __forceinline__ int afrag_idx(int m, int k) {
    int rb = m >> 4, m16 = m & 15, lr = m16 & 7, er = m16 >> 3;
    int kstep = k >> 3, k8 = k & 7, la3 = k8 & 3, ec = k8 >> 2;
    return ((((kstep << 3) + rb) * 32 + (lr << 2) + la3) << 2) + er + (ec << 1);
}

// B-fragment-major float index, wn in 32-col groups (R7 layout, verified).
// float4 idx = ((kstep*4 + wn)*2 + jp)*32 + lane ; elem = (j&1)*2 + (k8>=4)
__device__ __forceinline__ int bfrag_idx(int row, int k) {
    int wn = row >> 5, j = (row & 31) >> 3, lr = row & 7;
    int kstep = k >> 3, la3 = k & 3, b1 = ((k & 7) >= 4);
    return (((((kstep << 2) + wn) << 1) + (j >> 1)) * 32 + (lr << 2) + la3) * 4
           + ((j & 1) << 1) + b1;
}

// ---------------------------------------------------------------------------
// Kernel A: hidden = relu(x @ W_hidden^T + b_hidden), tf32-rounded,
//           written in A-fragment-major tile layout g_hfrag[h][mt][...]
// ---------------------------------------------------------------------------
__global__ void __launch_bounds__(256)
hidden_gemm(const float* __restrict__ x,
            const float* __restrict__ Wh,
            const float* __restrict__ bh)
{
    __shared__ float As[BM][SST];
    __shared__ float Bs[BN][SST];

    const int mtile = blockIdx.x & 7;
    const int ntile = blockIdx.x >> 3;       // head index
    const int m0 = mtile * BM;
    const int n0 = ntile * BN;

    const int tid  = threadIdx.x;
    const int lane = tid & 31;
    const int warp = tid >> 5;
    const int wm = warp >> 1;
    const int wn = warp & 1;

    float acc[2][8][4];
    #pragma unroll
    for (int t = 0; t < 2; ++t)
        #pragma unroll
        for (int j = 0; j < 8; ++j)
            #pragma unroll
            for (int q = 0; q < 4; ++q) acc[t][j][q] = 0.f;

    for (int k0 = 0; k0 < DIN; k0 += BK) {
        #pragma unroll
        for (int it = 0; it < 4; ++it) {
            int slot = tid + it * 256;
            int r  = slot >> 3;
            int c4 = (slot & 7) * 4;
            float4 va = *reinterpret_cast<const float4*>(
                x + (size_t)(m0 + r) * DIN + k0 + c4);
            As[r][c4 + 0] = __uint_as_float(f2tf32(va.x));
            As[r][c4 + 1] = __uint_as_float(f2tf32(va.y));
            As[r][c4 + 2] = __uint_as_float(f2tf32(va.z));
            As[r][c4 + 3] = __uint_as_float(f2tf32(va.w));
            float4 vb = *reinterpret_cast<const float4*>(
                Wh + (size_t)(n0 + r) * DIN + k0 + c4);
            Bs[r][c4 + 0] = __uint_as_float(f2tf32(vb.x));
            Bs[r][c4 + 1] = __uint_as_float(f2tf32(vb.y));
            Bs[r][c4 + 2] = __uint_as_float(f2tf32(vb.z));
            Bs[r][c4 + 3] = __uint_as_float(f2tf32(vb.w));
        }
        __syncthreads();

        #pragma unroll
        for (int ks = 0; ks < BK; ks += 8) {
            uint32_t a[2][4];
            #pragma unroll
            for (int t = 0; t < 2; ++t) {
                int row = wm * 32 + t * 16 + (lane >> 2);
                int kc  = ks + (lane & 3);
                a[t][0] = __float_as_uint(As[row][kc]);
                a[t][1] = __float_as_uint(As[row + 8][kc]);
                a[t][2] = __float_as_uint(As[row][kc + 4]);
                a[t][3] = __float_as_uint(As[row + 8][kc + 4]);
            }
            #pragma unroll
            for (int j = 0; j < 8; ++j) {
                int col = wn * 64 + j * 8 + (lane >> 2);
                int kc  = ks + (lane & 3);
                uint32_t b[2];
                b[0] = __float_as_uint(Bs[col][kc]);
                b[1] = __float_as_uint(Bs[col][kc + 4]);
                mma_tf32(acc[0][j], a[0], b);
                mma_tf32(acc[1][j], a[1], b);
            }
        }
        __syncthreads();
    }

    // Epilogue: bias + relu + tf32 round, scatter into A-fragment-major tile.
    float* Hf = g_hfrag + ((size_t)ntile * MTILES + mtile) * TILE_FLOATS;
    const int lr2  = lane >> 2;
    const int la32 = lane & 3;
    #pragma unroll
    for (int t = 0; t < 2; ++t) {
        #pragma unroll
        for (int j = 0; j < 8; ++j) {
            int kbase = wn * 64 + j * 8 + 2 * la32;
            float b0 = bh[n0 + kbase], b1 = bh[n0 + kbase + 1];
            int mA = wm * 32 + t * 16 + lr2;        // rows mA, mA+8
            Hf[afrag_idx(mA,     kbase    )] =
                __uint_as_float(f2tf32(fmaxf(acc[t][j][0] + b0, 0.f)));
            Hf[afrag_idx(mA,     kbase + 1)] =
                __uint_as_float(f2tf32(fmaxf(acc[t][j][1] + b1, 0.f)));
            Hf[afrag_idx(mA + 8, kbase    )] =
                __uint_as_float(f2tf32(fmaxf(acc[t][j][2] + b0, 0.f)));
            Hf[afrag_idx(mA + 8, kbase + 1)] =
                __uint_as_float(f2tf32(fmaxf(acc[t][j][3] + b1, 0.f)));
        }
    }
}

// ---------------------------------------------------------------------------
// Kernel B: 512 threads (16 warps, 4/SMSP), warp tile 32x32.
//   One CTA per N-tile, 8 M-tiles. B fragment-major resident; A full tiles
//   double-buffered via cp.async. One wait+sync per M-tile. Explicit 1-deep
//   register pipeline (R6 structure).
// ---------------------------------------------------------------------------
__global__ void __launch_bounds__(512, 1)
head_gemm(const float* __restrict__ Wheads,
          const float* __restrict__ bheads,
          float* __restrict__ out)
{
    extern __shared__ float smem[];
    float* sB = smem;                         // 16384 floats
    float* sA = smem + TILE_FLOATS;           // 2 x 16384 floats

    const int ntg = blockIdx.x;
    int h = 0;
    #pragma unroll
    for (int i = 1; i < NUM_HEADS; ++i) h += (ntg >= c_tile_start[i]);
    const int ntile = ntg - c_tile_start[h];
    const int p  = c_p[h];
    const int n0 = ntile * BN;

    const float* Bg    = Wheads + (size_t)h * PMAX * DSLICE;
    const float* bias  = bheads + (size_t)h * PMAX;
    float* Og = out + (size_t)c_cum[h] * BROWS;
    const float* Hf = g_hfrag + (size_t)h * MTILES * TILE_FLOATS;

    const int tid  = threadIdx.x;
    const int lane = tid & 31;
    const int warp = tid >> 5;
    const int wm = warp >> 2;   // 0..3 (32 rows each)
    const int wn = warp & 3;    // 0..3 (32 cols each)
    const int la3 = lane & 3;
    const int lr  = lane >> 2;

    const uint32_t sA_u = (uint32_t)__cvta_generic_to_shared(sA);

    // prefetch A tile 0 (contiguous 64KB)
    #pragma unroll
    for (int it = 0; it < 8; ++it) {
        int fo = (it * 512 + tid) * 4;
        cp_async16_s(sA_u + fo * 4, Hf + fo);
    }
    asm volatile("cp.async.commit_group;\n");

    // load B tile once -> fragment-major smem
    #pragma unroll
    for (int it = 0; it < 8; ++it) {
        int slot = it * 512 + tid;
        int row = slot >> 5;
        int k4  = (slot & 31) * 4;
        float4 v;
        if (n0 + row < p) {
            v = *reinterpret_cast<const float4*>(Bg + (size_t)(n0 + row) * DSLICE + k4);
        } else {
            v = make_float4(0.f, 0.f, 0.f, 0.f);
        }
        sB[bfrag_idx(row, k4    )] = __uint_as_float(f2tf32(v.x));
        sB[bfrag_idx(row, k4 + 1)] = __uint_as_float(f2tf32(v.y));
        sB[bfrag_idx(row, k4 + 2)] = __uint_as_float(f2tf32(v.z));
        sB[bfrag_idx(row, k4 + 3)] = __uint_as_float(f2tf32(v.w));
    }

    // hoist bias (same columns for every M-tile)
    float bs0[4], bs1[4];
    #pragma unroll
    for (int j = 0; j < 4; ++j) {
        int col = n0 + wn * 32 + j * 8 + 2 * la3;
        bs0[j] = (col < p) ? bias[col]     : 0.f;
        bs1[j] = (col < p) ? bias[col + 1] : 0.f;
    }

    const float4* sB4 = reinterpret_cast<const float4*>(sB);

    asm volatile("cp.async.wait_group 0;\n" ::: "memory");
    __syncthreads();

    for (int mt = 0; mt < MTILES; ++mt) {
        // prefetch next A tile into the other buffer
        if (mt + 1 < MTILES) {
            const float* src = Hf + (size_t)(mt + 1) * TILE_FLOATS;
            uint32_t dst = sA_u + (uint32_t)(((mt + 1) & 1) ? TILE_FLOATS * 4 : 0);
            #pragma unroll
            for (int it = 0; it < 8; ++it) {
                int fo = (it * 512 + tid) * 4;
                cp_async16_s(dst + fo * 4, src + fo);
            }
            asm volatile("cp.async.commit_group;\n");
        }

        const float4* sA4 = reinterpret_cast<const float4*>(
            sA + (mt & 1) * TILE_FLOATS);

        float acc[2][4][4];
        #pragma unroll
        for (int t = 0; t < 2; ++t)
            #pragma unroll
            for (int j = 0; j < 4; ++j)
                #pragma unroll
                for (int q = 0; q < 4; ++q) acc[t][j][q] = 0.f;

        // explicit 1-deep register pipeline
        float4 a_cur[2], a_nxt[2], b_cur[2], b_nxt[2];
        #pragma unroll
        for (int t = 0; t < 2; ++t)
            a_cur[t] = sA4[(wm * 2 + t) * 32 + lane];
        b_cur[0] = sB4[(wn * 2 + 0) * 32 + lane];
        b_cur[1] = sB4[(wn * 2 + 1) * 32 + lane];

        #pragma unroll
        for (int ks = 0; ks < 16; ++ks) {
            if (ks + 1 < 16) {
                #pragma unroll
                for (int t = 0; t < 2; ++t)
                    a_nxt[t] = sA4[((ks + 1) * 8 + wm * 2 + t) * 32 + lane];
                b_nxt[0] = sB4[(((ks + 1) * 4 + wn) * 2 + 0) * 32 + lane];
                b_nxt[1] = sB4[(((ks + 1) * 4 + wn) * 2 + 1) * 32 + lane];
            }
            const uint32_t* a0 = reinterpret_cast<const uint32_t*>(&a_cur[0]);
            const uint32_t* a1 = reinterpret_cast<const uint32_t*>(&a_cur[1]);
            #pragma unroll
            for (int jp = 0; jp < 2; ++jp) {
                const uint32_t* bp = reinterpret_cast<const uint32_t*>(&b_cur[jp]);
                uint32_t bj0[2] = {bp[0], bp[1]};
                uint32_t bj1[2] = {bp[2], bp[3]};
                mma_tf32(acc[0][jp * 2],     a0, bj0);
                mma_tf32(acc[1][jp * 2],     a1, bj0);
                mma_tf32(acc[0][jp * 2 + 1], a0, bj1);
                mma_tf32(acc[1][jp * 2 + 1], a1, bj1);
            }
            a_cur[0] = a_nxt[0]; a_cur[1] = a_nxt[1];
            b_cur[0] = b_nxt[0]; b_cur[1] = b_nxt[1];
        }

        // epilogue
        const int m0 = mt * BM;
        #pragma unroll
        for (int t = 0; t < 2; ++t) {
            int row = m0 + wm * 32 + t * 16 + lr;
            #pragma unroll
            for (int j = 0; j < 4; ++j) {
                int col = n0 + wn * 32 + j * 8 + 2 * la3;
                if (col < p) {
                    float2 v0 = make_float2(acc[t][j][0] + bs0[j], acc[t][j][1] + bs1[j]);
                    float2 v1 = make_float2(acc[t][j][2] + bs0[j], acc[t][j][3] + bs1[j]);
                    *reinterpret_cast<float2*>(&Og[(size_t)row * p + col])       = v0;
                    *reinterpret_cast<float2*>(&Og[(size_t)(row + 8) * p + col]) = v1;
                }
            }
        }

        // A(mt+1) ready before next compute; sync also protects buffer reuse
        asm volatile("cp.async.wait_group 0;\n" ::: "memory");
        __syncthreads();
    }
}

} // anonymous namespace

extern "C" void kernel_launch(void* const* d_in, const int* in_sizes, int n_in,
                              void* d_out, int out_size) {
    (void)in_sizes; (void)n_in; (void)out_size;
    const float* x      = (const float*)d_in[0];
    const float* Wh     = (const float*)d_in[1];
    const float* bh     = (const float*)d_in[2];
    const float* Wheads = (const float*)d_in[3];
    const float* bheads = (const float*)d_in[4];
    float* out = (float*)d_out;

    static bool attr_set = false;
    if (!attr_set) {
        cudaFuncSetAttribute(head_gemm,
                             cudaFuncAttributeMaxDynamicSharedMemorySize,
                             (int)HEAD_SMEM_BYTES);
        attr_set = true;
    }

    hidden_gemm<<<MTILES * (HID / BN), 256>>>(x, Wh, bh);
    head_gemm<<<TOTAL_NTILES, 512, HEAD_SMEM_BYTES>>>(Wheads, bheads, out);
}